// round 1
// baseline (speedup 1.0000x reference)
#include <cuda_runtime.h>
#include <cuda_bf16.h>
#include <cstdint>

// Problem constants (fixed shapes per reference)
#define BATCH 8
#define SLEN 1024
#define DMODEL 1024
#define NHEADS 16
#define HDIM 64
#define MROWS (BATCH * SLEN)       // 8192
#define QKV_N (3 * DMODEL)         // 3072
#define LN_EPS 1e-5f

// Scratch (static device globals: allocation-free rule)
__device__ float g_qkv[(size_t)MROWS * QKV_N];    // [8192, 3072]
__device__ float g_attn[(size_t)MROWS * DMODEL];  // [8192, 1024]

// ---------------------------------------------------------------------------
// GEMM: C[M,N] = A[M,K] @ B[K,N] + bias[N] (+ res[M,N] if RESID)
// BM=BN=128, BK=16, 256 threads, 8x8 per-thread tile. Shapes divide evenly.
// ---------------------------------------------------------------------------
#define BM 128
#define BN 128
#define BK 16
#define TM 8
#define TN 8

template <bool RESID>
__global__ __launch_bounds__(256) void gemm_kernel(
    const float* __restrict__ A, const float* __restrict__ B,
    const float* __restrict__ bias, const float* __restrict__ res,
    float* __restrict__ C, int M, int N, int K)
{
    __shared__ float As[BK][BM];   // A stored transposed: As[k][m]
    __shared__ float Bs[BK][BN];

    const int tid = threadIdx.x;
    const int tn = tid & 15;       // 0..15
    const int tm = tid >> 4;       // 0..15
    const int block_m = blockIdx.y * BM;
    const int block_n = blockIdx.x * BN;

    // A tile loader: 128 rows x 16 k = 512 float4 (4 k each) -> 2 per thread
    const int a_r = tid >> 2;            // 0..63 (rows a_r, a_r+64)
    const int a_c = (tid & 3) * 4;       // k offset 0,4,8,12
    // B tile loader: 16 rows x 128 n = 512 float4 -> 2 per thread
    const int b_r = tid >> 5;            // 0..7 (rows b_r, b_r+8)
    const int b_c = (tid & 31) * 4;      // n offset

    float acc[TM][TN];
    #pragma unroll
    for (int i = 0; i < TM; i++)
        #pragma unroll
        for (int j = 0; j < TN; j++) acc[i][j] = 0.0f;

    const float* Aptr = A + (size_t)block_m * K;
    const float* Bptr = B + block_n;

    for (int k0 = 0; k0 < K; k0 += BK) {
        #pragma unroll
        for (int i = 0; i < 2; i++) {
            int r = a_r + i * 64;
            float4 v = *(const float4*)(Aptr + (size_t)r * K + k0 + a_c);
            As[a_c + 0][r] = v.x;
            As[a_c + 1][r] = v.y;
            As[a_c + 2][r] = v.z;
            As[a_c + 3][r] = v.w;
        }
        #pragma unroll
        for (int i = 0; i < 2; i++) {
            int r = b_r + i * 8;
            *(float4*)&Bs[r][b_c] =
                *(const float4*)(Bptr + (size_t)(k0 + r) * N + b_c);
        }
        __syncthreads();

        #pragma unroll
        for (int kk = 0; kk < BK; kk++) {
            float a[TM], b[TN];
            #pragma unroll
            for (int i = 0; i < TM; i += 4)
                *(float4*)&a[i] = *(const float4*)&As[kk][tm * TM + i];
            #pragma unroll
            for (int j = 0; j < TN; j += 4)
                *(float4*)&b[j] = *(const float4*)&Bs[kk][tn * TN + j];
            #pragma unroll
            for (int i = 0; i < TM; i++)
                #pragma unroll
                for (int j = 0; j < TN; j++)
                    acc[i][j] += a[i] * b[j];
        }
        __syncthreads();
    }

    // Epilogue: bias (+ residual) and store
    #pragma unroll
    for (int i = 0; i < TM; i++) {
        const int m = block_m + tm * TM + i;
        float* crow = C + (size_t)m * N + block_n + tn * TN;
        #pragma unroll
        for (int j = 0; j < TN; j += 4) {
            const int n = block_n + tn * TN + j;
            float4 o;
            o.x = acc[i][j + 0] + bias[n + 0];
            o.y = acc[i][j + 1] + bias[n + 1];
            o.z = acc[i][j + 2] + bias[n + 2];
            o.w = acc[i][j + 3] + bias[n + 3];
            if (RESID) {
                float4 rv = *(const float4*)(res + (size_t)m * N + n);
                o.x += rv.x; o.y += rv.y; o.z += rv.z; o.w += rv.w;
            }
            *(float4*)(crow + j) = o;
        }
    }
}

// ---------------------------------------------------------------------------
// Flash-style causal attention.
// Grid: (S/64, H, B), 64 threads/block; thread t owns query row qt*64+t.
// Q row (scaled) + O accumulator live in registers (64 + 64 floats).
// K/V tiles staged in smem; score-loop reads of Ks[j][*] are uniform across
// the warp (broadcast, conflict-free unpadded). Scores staged transposed in
// Ss[j][tid] (lane-indexed -> conflict-free) to fit 48KB static smem exactly.
// ---------------------------------------------------------------------------
#define AT 64

__global__ __launch_bounds__(64) void attn_kernel(
    const float* __restrict__ qkv, float* __restrict__ out)
{
    __shared__ float Ks[AT][HDIM];
    __shared__ float Vs[AT][HDIM];
    __shared__ float Ss[AT][AT];   // Ss[j][tid]

    const int tid = threadIdx.x;
    const int qt = blockIdx.x;
    const int h  = blockIdx.y;
    const int b  = blockIdx.z;
    const int q  = qt * AT + tid;
    const size_t rowstride = QKV_N;

    const float scale = 0.03125f;  // 1/sqrt(1024)

    // Load + scale Q row into registers
    const float* qbase = qkv + ((size_t)(b * SLEN + q)) * rowstride + h * HDIM;
    float4 qreg[HDIM / 4];
    #pragma unroll
    for (int c = 0; c < HDIM / 4; c++) {
        float4 v = *(const float4*)(qbase + c * 4);
        v.x *= scale; v.y *= scale; v.z *= scale; v.w *= scale;
        qreg[c] = v;
    }

    float4 o[HDIM / 4];
    #pragma unroll
    for (int c = 0; c < HDIM / 4; c++) o[c] = make_float4(0.f, 0.f, 0.f, 0.f);
    float m_i = -1e30f, l_i = 0.0f;

    for (int kt = 0; kt <= qt; kt++) {
        const float* kbase = qkv + ((size_t)(b * SLEN + kt * AT)) * rowstride
                             + DMODEL + h * HDIM;
        const float* vbase = kbase + DMODEL;
        // cooperative tile load: i -> (row, float4-col); lanes coalesce in col
        for (int i = tid; i < AT * (HDIM / 4); i += 64) {
            int r = i >> 4;          // /16
            int c = (i & 15) * 4;
            *(float4*)&Ks[r][c] = *(const float4*)(kbase + (size_t)r * rowstride + c);
            *(float4*)&Vs[r][c] = *(const float4*)(vbase + (size_t)r * rowstride + c);
        }
        __syncthreads();

        const bool diag = (kt == qt);
        float m_new = m_i;
        #pragma unroll 4
        for (int j = 0; j < AT; j++) {
            float acc = 0.0f;
            #pragma unroll
            for (int c = 0; c < HDIM / 4; c++) {
                float4 kv = *(const float4*)&Ks[j][c * 4];
                acc += qreg[c].x * kv.x + qreg[c].y * kv.y
                     + qreg[c].z * kv.z + qreg[c].w * kv.w;
            }
            if (diag && j > tid) acc = -1e30f;
            Ss[j][tid] = acc;
            m_new = fmaxf(m_new, acc);
        }

        const float corr = __expf(m_i - m_new);
        l_i *= corr;
        #pragma unroll
        for (int c = 0; c < HDIM / 4; c++) {
            o[c].x *= corr; o[c].y *= corr; o[c].z *= corr; o[c].w *= corr;
        }

        #pragma unroll 2
        for (int j = 0; j < AT; j++) {
            float p = __expf(Ss[j][tid] - m_new);
            l_i += p;
            #pragma unroll
            for (int c = 0; c < HDIM / 4; c++) {
                float4 vv = *(const float4*)&Vs[j][c * 4];
                o[c].x += p * vv.x; o[c].y += p * vv.y;
                o[c].z += p * vv.z; o[c].w += p * vv.w;
            }
        }
        m_i = m_new;
        __syncthreads();
    }

    const float inv = 1.0f / l_i;
    float* obase = out + ((size_t)(b * SLEN + q)) * DMODEL + h * HDIM;
    #pragma unroll
    for (int c = 0; c < HDIM / 4; c++) {
        float4 w = o[c];
        w.x *= inv; w.y *= inv; w.z *= inv; w.w *= inv;
        *(float4*)(obase + c * 4) = w;
    }
}

// ---------------------------------------------------------------------------
// LayerNorm over last dim, in-place. One block (256 thr) per row of 1024.
// ---------------------------------------------------------------------------
__global__ __launch_bounds__(256) void ln_kernel(
    float* __restrict__ io, const float* __restrict__ gamma,
    const float* __restrict__ beta)
{
    const int row = blockIdx.x;
    const int tid = threadIdx.x;
    float4* p = (float4*)(io + (size_t)row * DMODEL);
    float4 v = p[tid];

    float s  = v.x + v.y + v.z + v.w;
    float s2 = fmaf(v.x, v.x, fmaf(v.y, v.y, fmaf(v.z, v.z, v.w * v.w)));

    #pragma unroll
    for (int ofs = 16; ofs; ofs >>= 1) {
        s  += __shfl_xor_sync(0xffffffffu, s, ofs);
        s2 += __shfl_xor_sync(0xffffffffu, s2, ofs);
    }
    __shared__ float shs[8], shs2[8];
    const int w = tid >> 5, l = tid & 31;
    if (l == 0) { shs[w] = s; shs2[w] = s2; }
    __syncthreads();
    if (tid < 32) {
        float a  = (l < 8) ? shs[l]  : 0.0f;
        float a2 = (l < 8) ? shs2[l] : 0.0f;
        #pragma unroll
        for (int ofs = 4; ofs; ofs >>= 1) {
            a  += __shfl_xor_sync(0xffffffffu, a, ofs);
            a2 += __shfl_xor_sync(0xffffffffu, a2, ofs);
        }
        if (l == 0) { shs[0] = a; shs2[0] = a2; }
    }
    __syncthreads();

    const float mean = shs[0] * (1.0f / DMODEL);
    const float var  = shs2[0] * (1.0f / DMODEL) - mean * mean;
    const float rstd = rsqrtf(var + LN_EPS);

    float4 g  = ((const float4*)gamma)[tid];
    float4 be = ((const float4*)beta)[tid];
    float4 r;
    r.x = (v.x - mean) * rstd * g.x + be.x;
    r.y = (v.y - mean) * rstd * g.y + be.y;
    r.z = (v.z - mean) * rstd * g.z + be.z;
    r.w = (v.w - mean) * rstd * g.w + be.w;
    p[tid] = r;
}

// ---------------------------------------------------------------------------
extern "C" void kernel_launch(void* const* d_in, const int* in_sizes, int n_in,
                              void* d_out, int out_size)
{
    const float* x     = (const float*)d_in[0];
    const float* Wqkv  = (const float*)d_in[1];
    const float* bqkv  = (const float*)d_in[2];
    const float* Wout  = (const float*)d_in[3];
    const float* bout  = (const float*)d_in[4];
    const float* gamma = (const float*)d_in[5];
    const float* beta  = (const float*)d_in[6];
    float* out = (float*)d_out;

    float* qkv;  cudaGetSymbolAddress((void**)&qkv,  g_qkv);
    float* attn; cudaGetSymbolAddress((void**)&attn, g_attn);

    // 1) QKV projection: [8192,1024] @ [1024,3072] + bias
    {
        dim3 grid(QKV_N / BN, MROWS / BM);
        gemm_kernel<false><<<grid, 256>>>(x, Wqkv, bqkv, nullptr, qkv,
                                          MROWS, QKV_N, DMODEL);
    }
    // 2) causal flash attention
    {
        dim3 grid(SLEN / AT, NHEADS, BATCH);
        attn_kernel<<<grid, 64>>>(qkv, attn);
    }
    // 3) out projection + bias + residual
    {
        dim3 grid(DMODEL / BN, MROWS / BM);
        gemm_kernel<true><<<grid, 256>>>(attn, Wout, bout, x, out,
                                         MROWS, DMODEL, DMODEL);
    }
    // 4) LayerNorm in-place on d_out
    ln_kernel<<<MROWS, 256>>>(out, gamma, beta);
}

// round 2
// speedup vs baseline: 1.6246x; 1.6246x over previous
#include <cuda_runtime.h>
#include <cuda_bf16.h>
#include <cstdint>

#define BATCH 8
#define SLEN 1024
#define DMODEL 1024
#define NHEADS 16
#define HDIM 64
#define MROWS (BATCH * SLEN)       // 8192
#define QKV_N (3 * DMODEL)         // 3072
#define LN_EPS 1e-5f

typedef __nv_bfloat16 bf;

// Scratch (static device globals: allocation-free rule)
__device__ float g_qkv[(size_t)MROWS * QKV_N];        // fp32 QKV for attention
__device__ bf g_xhi[(size_t)MROWS * DMODEL];
__device__ bf g_xlo[(size_t)MROWS * DMODEL];
__device__ bf g_wqkv_hi[(size_t)DMODEL * QKV_N];
__device__ bf g_wqkv_lo[(size_t)DMODEL * QKV_N];
__device__ bf g_wout_hi[(size_t)DMODEL * DMODEL];
__device__ bf g_wout_lo[(size_t)DMODEL * DMODEL];
__device__ bf g_attn_hi[(size_t)MROWS * DMODEL];
__device__ bf g_attn_lo[(size_t)MROWS * DMODEL];

// ---------------------------------------------------------------------------
// fp32 -> (bf16 hi, bf16 lo) split conversion, vectorized by 4
// ---------------------------------------------------------------------------
__global__ __launch_bounds__(256) void cvt_kernel(
    const float4* __restrict__ in, uint2* __restrict__ hi,
    uint2* __restrict__ lo, int n4)
{
    int i = blockIdx.x * blockDim.x + threadIdx.x;
    if (i >= n4) return;
    float4 v = in[i];
    bf h0 = __float2bfloat16(v.x);
    bf h1 = __float2bfloat16(v.y);
    bf h2 = __float2bfloat16(v.z);
    bf h3 = __float2bfloat16(v.w);
    bf l0 = __float2bfloat16(v.x - __bfloat162float(h0));
    bf l1 = __float2bfloat16(v.y - __bfloat162float(h1));
    bf l2 = __float2bfloat16(v.z - __bfloat162float(h2));
    bf l3 = __float2bfloat16(v.w - __bfloat162float(h3));
    __nv_bfloat162 hp0 = __halves2bfloat162(h0, h1);
    __nv_bfloat162 hp1 = __halves2bfloat162(h2, h3);
    __nv_bfloat162 lp0 = __halves2bfloat162(l0, l1);
    __nv_bfloat162 lp1 = __halves2bfloat162(l2, l3);
    uint2 ho, loo;
    ho.x = *(uint32_t*)&hp0;  ho.y = *(uint32_t*)&hp1;
    loo.x = *(uint32_t*)&lp0; loo.y = *(uint32_t*)&lp1;
    hi[i] = ho;
    lo[i] = loo;
}

// ---------------------------------------------------------------------------
// Tensor-core GEMM with bf16x2-split inputs (3 MMAs per fp32-equivalent MAC).
// C[M,N] = A[M,K] @ B[K,N] + bias (+res). BM=BN=128, BK=32, 256 thr, 8 warps
// each owning a 64x32 warp tile of m16n8k16 MMAs.
// ---------------------------------------------------------------------------
#define BM 128
#define BN 128
#define BK 32
#define APAD 8
#define BPAD 8

__device__ __forceinline__ uint32_t cvta_smem(const void* p) {
    uint32_t a;
    asm("{.reg .u64 t; cvta.to.shared.u64 t, %1; cvt.u32.u64 %0, t;}"
        : "=r"(a) : "l"(p));
    return a;
}
__device__ __forceinline__ void ldsm4(uint32_t a, uint32_t& r0, uint32_t& r1,
                                      uint32_t& r2, uint32_t& r3) {
    asm volatile("ldmatrix.sync.aligned.m8n8.x4.shared.b16 {%0,%1,%2,%3},[%4];"
                 : "=r"(r0), "=r"(r1), "=r"(r2), "=r"(r3) : "r"(a));
}
__device__ __forceinline__ void ldsm4t(uint32_t a, uint32_t& r0, uint32_t& r1,
                                       uint32_t& r2, uint32_t& r3) {
    asm volatile("ldmatrix.sync.aligned.m8n8.x4.trans.shared.b16 {%0,%1,%2,%3},[%4];"
                 : "=r"(r0), "=r"(r1), "=r"(r2), "=r"(r3) : "r"(a));
}
__device__ __forceinline__ void mma_bf16(float* c, const uint32_t* a,
                                         const uint32_t* b) {
    asm volatile(
        "mma.sync.aligned.m16n8k16.row.col.f32.bf16.bf16.f32 "
        "{%0,%1,%2,%3},{%4,%5,%6,%7},{%8,%9},{%0,%1,%2,%3};"
        : "+f"(c[0]), "+f"(c[1]), "+f"(c[2]), "+f"(c[3])
        : "r"(a[0]), "r"(a[1]), "r"(a[2]), "r"(a[3]), "r"(b[0]), "r"(b[1]));
}

template <bool RESID>
__global__ __launch_bounds__(256, 1) void mma_gemm(
    const bf* __restrict__ Ahi, const bf* __restrict__ Alo,
    const bf* __restrict__ Bhi, const bf* __restrict__ Blo,
    const float* __restrict__ bias, const float* __restrict__ res,
    float* __restrict__ C, int M, int N, int K)
{
    __shared__ bf Ash[2][BM][BK + APAD];   // [hi/lo][m][k]
    __shared__ bf Bsh[2][BK][BN + BPAD];   // [hi/lo][k][n]

    const int tid = threadIdx.x;
    const int lane = tid & 31;
    const int warp = tid >> 5;
    const int wm = warp >> 2;   // 0..1 -> 64 rows
    const int wn = warp & 3;    // 0..3 -> 32 cols
    const int bm0 = blockIdx.y * BM;
    const int bn0 = blockIdx.x * BN;

    // gmem tile loader mapping
    const int ar = tid >> 2;          // 0..63 (rows ar, ar+64)
    const int ac = (tid & 3) * 8;     // k offset
    const int br = tid >> 3;          // 0..31
    const int bc = (tid & 7) * 16;    // n offset

    float acc[4][4][4];
    #pragma unroll
    for (int i = 0; i < 4; i++)
        #pragma unroll
        for (int j = 0; j < 4; j++)
            #pragma unroll
            for (int c = 0; c < 4; c++) acc[i][j][c] = 0.0f;

    const bf* Ah = Ahi + (size_t)(bm0 + ar) * K + ac;
    const bf* Al = Alo + (size_t)(bm0 + ar) * K + ac;
    const bf* Bh = Bhi + (size_t)br * N + bn0 + bc;
    const bf* Bl = Blo + (size_t)br * N + bn0 + bc;

    uint4 pa[4], pb[4];
    pa[0] = *(const uint4*)(Ah);
    pa[1] = *(const uint4*)(Ah + (size_t)64 * K);
    pa[2] = *(const uint4*)(Al);
    pa[3] = *(const uint4*)(Al + (size_t)64 * K);
    pb[0] = *(const uint4*)(Bh);
    pb[1] = *(const uint4*)(Bh + 8);
    pb[2] = *(const uint4*)(Bl);
    pb[3] = *(const uint4*)(Bl + 8);

    const int iters = K / BK;
    for (int it = 0; it < iters; it++) {
        {   // stage prefetched tile into smem (uint2 stores: 8B-aligned w/ pad)
            uint2* d; const uint2* s;
            d = (uint2*)&Ash[0][ar][ac];      s = (const uint2*)&pa[0]; d[0]=s[0]; d[1]=s[1];
            d = (uint2*)&Ash[0][ar+64][ac];   s = (const uint2*)&pa[1]; d[0]=s[0]; d[1]=s[1];
            d = (uint2*)&Ash[1][ar][ac];      s = (const uint2*)&pa[2]; d[0]=s[0]; d[1]=s[1];
            d = (uint2*)&Ash[1][ar+64][ac];   s = (const uint2*)&pa[3]; d[0]=s[0]; d[1]=s[1];
            d = (uint2*)&Bsh[0][br][bc];      s = (const uint2*)&pb[0]; d[0]=s[0]; d[1]=s[1];
            d = (uint2*)&Bsh[0][br][bc+8];    s = (const uint2*)&pb[1]; d[0]=s[0]; d[1]=s[1];
            d = (uint2*)&Bsh[1][br][bc];      s = (const uint2*)&pb[2]; d[0]=s[0]; d[1]=s[1];
            d = (uint2*)&Bsh[1][br][bc+8];    s = (const uint2*)&pb[3]; d[0]=s[0]; d[1]=s[1];
        }
        __syncthreads();

        if (it + 1 < iters) {   // prefetch next tile (overlaps with MMAs)
            const size_t ka = (size_t)(it + 1) * BK;
            pa[0] = *(const uint4*)(Ah + ka);
            pa[1] = *(const uint4*)(Ah + (size_t)64 * K + ka);
            pa[2] = *(const uint4*)(Al + ka);
            pa[3] = *(const uint4*)(Al + (size_t)64 * K + ka);
            const size_t kb = ka * N;
            pb[0] = *(const uint4*)(Bh + kb);
            pb[1] = *(const uint4*)(Bh + kb + 8);
            pb[2] = *(const uint4*)(Bl + kb);
            pb[3] = *(const uint4*)(Bl + kb + 8);
        }

        #pragma unroll
        for (int kk = 0; kk < 2; kk++) {
            uint32_t ah[4][4], al[4][4], bh[4][2], bl[4][2];
            const int arow = wm * 64 + (lane & 15);
            const int acol = kk * 16 + (lane >> 4) * 8;
            #pragma unroll
            for (int mt = 0; mt < 4; mt++) {
                ldsm4(cvta_smem(&Ash[0][arow + mt * 16][acol]),
                      ah[mt][0], ah[mt][1], ah[mt][2], ah[mt][3]);
                ldsm4(cvta_smem(&Ash[1][arow + mt * 16][acol]),
                      al[mt][0], al[mt][1], al[mt][2], al[mt][3]);
            }
            const int brow = kk * 16 + (lane & 15);
            #pragma unroll
            for (int ng = 0; ng < 2; ng++) {
                const int bcol = wn * 32 + ng * 16 + (lane >> 4) * 8;
                ldsm4t(cvta_smem(&Bsh[0][brow][bcol]),
                       bh[2*ng][0], bh[2*ng][1], bh[2*ng+1][0], bh[2*ng+1][1]);
                ldsm4t(cvta_smem(&Bsh[1][brow][bcol]),
                       bl[2*ng][0], bl[2*ng][1], bl[2*ng+1][0], bl[2*ng+1][1]);
            }
            #pragma unroll
            for (int mt = 0; mt < 4; mt++)
                #pragma unroll
                for (int nt = 0; nt < 4; nt++) {
                    mma_bf16(acc[mt][nt], ah[mt], bh[nt]);
                    mma_bf16(acc[mt][nt], ah[mt], bl[nt]);
                    mma_bf16(acc[mt][nt], al[mt], bh[nt]);
                }
        }
        __syncthreads();
    }

    // epilogue
    const int r0 = lane >> 2;
    const int cp = (lane & 3) * 2;
    #pragma unroll
    for (int mt = 0; mt < 4; mt++) {
        #pragma unroll
        for (int nt = 0; nt < 4; nt++) {
            const int gc = bn0 + wn * 32 + nt * 8 + cp;
            const float2 bv = *(const float2*)(bias + gc);
            #pragma unroll
            for (int h = 0; h < 2; h++) {
                const int gr = bm0 + wm * 64 + mt * 16 + r0 + h * 8;
                float2 o;
                o.x = acc[mt][nt][2 * h + 0] + bv.x;
                o.y = acc[mt][nt][2 * h + 1] + bv.y;
                if (RESID) {
                    float2 rv = *(const float2*)(res + (size_t)gr * N + gc);
                    o.x += rv.x; o.y += rv.y;
                }
                *(float2*)(C + (size_t)gr * N + gc) = o;
            }
        }
    }
}

// ---------------------------------------------------------------------------
// Flash-style causal attention (fp32 SIMT). Writes output directly as
// bf16 hi/lo split for the out-projection tensor-core GEMM.
// ---------------------------------------------------------------------------
#define AT 64

__global__ __launch_bounds__(64) void attn_kernel(
    const float* __restrict__ qkv, bf* __restrict__ out_hi,
    bf* __restrict__ out_lo)
{
    __shared__ float Ks[AT][HDIM];
    __shared__ float Vs[AT][HDIM];
    __shared__ float Ss[AT][AT];   // Ss[j][tid]

    const int tid = threadIdx.x;
    const int qt = blockIdx.x;
    const int h  = blockIdx.y;
    const int b  = blockIdx.z;
    const int q  = qt * AT + tid;
    const size_t rowstride = QKV_N;

    const float scale = 0.03125f;  // 1/sqrt(1024)

    const float* qbase = qkv + ((size_t)(b * SLEN + q)) * rowstride + h * HDIM;
    float4 qreg[HDIM / 4];
    #pragma unroll
    for (int c = 0; c < HDIM / 4; c++) {
        float4 v = *(const float4*)(qbase + c * 4);
        v.x *= scale; v.y *= scale; v.z *= scale; v.w *= scale;
        qreg[c] = v;
    }

    float4 o[HDIM / 4];
    #pragma unroll
    for (int c = 0; c < HDIM / 4; c++) o[c] = make_float4(0.f, 0.f, 0.f, 0.f);
    float m_i = -1e30f, l_i = 0.0f;

    for (int kt = 0; kt <= qt; kt++) {
        const float* kbase = qkv + ((size_t)(b * SLEN + kt * AT)) * rowstride
                             + DMODEL + h * HDIM;
        const float* vbase = kbase + DMODEL;
        for (int i = tid; i < AT * (HDIM / 4); i += 64) {
            int r = i >> 4;
            int c = (i & 15) * 4;
            *(float4*)&Ks[r][c] = *(const float4*)(kbase + (size_t)r * rowstride + c);
            *(float4*)&Vs[r][c] = *(const float4*)(vbase + (size_t)r * rowstride + c);
        }
        __syncthreads();

        const bool diag = (kt == qt);
        float m_new = m_i;
        #pragma unroll 4
        for (int j = 0; j < AT; j++) {
            float acc = 0.0f;
            #pragma unroll
            for (int c = 0; c < HDIM / 4; c++) {
                float4 kv = *(const float4*)&Ks[j][c * 4];
                acc += qreg[c].x * kv.x + qreg[c].y * kv.y
                     + qreg[c].z * kv.z + qreg[c].w * kv.w;
            }
            if (diag && j > tid) acc = -1e30f;
            Ss[j][tid] = acc;
            m_new = fmaxf(m_new, acc);
        }

        const float corr = __expf(m_i - m_new);
        l_i *= corr;
        #pragma unroll
        for (int c = 0; c < HDIM / 4; c++) {
            o[c].x *= corr; o[c].y *= corr; o[c].z *= corr; o[c].w *= corr;
        }

        #pragma unroll 2
        for (int j = 0; j < AT; j++) {
            float p = __expf(Ss[j][tid] - m_new);
            l_i += p;
            #pragma unroll
            for (int c = 0; c < HDIM / 4; c++) {
                float4 vv = *(const float4*)&Vs[j][c * 4];
                o[c].x += p * vv.x; o[c].y += p * vv.y;
                o[c].z += p * vv.z; o[c].w += p * vv.w;
            }
        }
        m_i = m_new;
        __syncthreads();
    }

    const float inv = 1.0f / l_i;
    const size_t obase = ((size_t)(b * SLEN + q)) * DMODEL + h * HDIM;
    #pragma unroll
    for (int c = 0; c < HDIM / 4; c++) {
        float4 w = o[c];
        w.x *= inv; w.y *= inv; w.z *= inv; w.w *= inv;
        bf h0 = __float2bfloat16(w.x);
        bf h1 = __float2bfloat16(w.y);
        bf h2 = __float2bfloat16(w.z);
        bf h3 = __float2bfloat16(w.w);
        bf l0 = __float2bfloat16(w.x - __bfloat162float(h0));
        bf l1 = __float2bfloat16(w.y - __bfloat162float(h1));
        bf l2 = __float2bfloat16(w.z - __bfloat162float(h2));
        bf l3 = __float2bfloat16(w.w - __bfloat162float(h3));
        __nv_bfloat162 hp0 = __halves2bfloat162(h0, h1);
        __nv_bfloat162 hp1 = __halves2bfloat162(h2, h3);
        __nv_bfloat162 lp0 = __halves2bfloat162(l0, l1);
        __nv_bfloat162 lp1 = __halves2bfloat162(l2, l3);
        uint2 hv, lv;
        hv.x = *(uint32_t*)&hp0; hv.y = *(uint32_t*)&hp1;
        lv.x = *(uint32_t*)&lp0; lv.y = *(uint32_t*)&lp1;
        *(uint2*)(out_hi + obase + c * 4) = hv;
        *(uint2*)(out_lo + obase + c * 4) = lv;
    }
}

// ---------------------------------------------------------------------------
// LayerNorm over last dim, in-place. One block (256 thr) per row of 1024.
// ---------------------------------------------------------------------------
__global__ __launch_bounds__(256) void ln_kernel(
    float* __restrict__ io, const float* __restrict__ gamma,
    const float* __restrict__ beta)
{
    const int row = blockIdx.x;
    const int tid = threadIdx.x;
    float4* p = (float4*)(io + (size_t)row * DMODEL);
    float4 v = p[tid];

    float s  = v.x + v.y + v.z + v.w;
    float s2 = fmaf(v.x, v.x, fmaf(v.y, v.y, fmaf(v.z, v.z, v.w * v.w)));

    #pragma unroll
    for (int ofs = 16; ofs; ofs >>= 1) {
        s  += __shfl_xor_sync(0xffffffffu, s, ofs);
        s2 += __shfl_xor_sync(0xffffffffu, s2, ofs);
    }
    __shared__ float shs[8], shs2[8];
    const int w = tid >> 5, l = tid & 31;
    if (l == 0) { shs[w] = s; shs2[w] = s2; }
    __syncthreads();
    if (tid < 32) {
        float a  = (l < 8) ? shs[l]  : 0.0f;
        float a2 = (l < 8) ? shs2[l] : 0.0f;
        #pragma unroll
        for (int ofs = 4; ofs; ofs >>= 1) {
            a  += __shfl_xor_sync(0xffffffffu, a, ofs);
            a2 += __shfl_xor_sync(0xffffffffu, a2, ofs);
        }
        if (l == 0) { shs[0] = a; shs2[0] = a2; }
    }
    __syncthreads();

    const float mean = shs[0] * (1.0f / DMODEL);
    const float var  = shs2[0] * (1.0f / DMODEL) - mean * mean;
    const float rstd = rsqrtf(var + LN_EPS);

    float4 g  = ((const float4*)gamma)[tid];
    float4 be = ((const float4*)beta)[tid];
    float4 r;
    r.x = (v.x - mean) * rstd * g.x + be.x;
    r.y = (v.y - mean) * rstd * g.y + be.y;
    r.z = (v.z - mean) * rstd * g.z + be.z;
    r.w = (v.w - mean) * rstd * g.w + be.w;
    p[tid] = r;
}

// ---------------------------------------------------------------------------
extern "C" void kernel_launch(void* const* d_in, const int* in_sizes, int n_in,
                              void* d_out, int out_size)
{
    const float* x     = (const float*)d_in[0];
    const float* Wqkv  = (const float*)d_in[1];
    const float* bqkv  = (const float*)d_in[2];
    const float* Wout  = (const float*)d_in[3];
    const float* bout  = (const float*)d_in[4];
    const float* gamma = (const float*)d_in[5];
    const float* beta  = (const float*)d_in[6];
    float* out = (float*)d_out;

    float* qkv;   cudaGetSymbolAddress((void**)&qkv,  g_qkv);
    bf* xhi;      cudaGetSymbolAddress((void**)&xhi,  g_xhi);
    bf* xlo;      cudaGetSymbolAddress((void**)&xlo,  g_xlo);
    bf* wqh;      cudaGetSymbolAddress((void**)&wqh,  g_wqkv_hi);
    bf* wql;      cudaGetSymbolAddress((void**)&wql,  g_wqkv_lo);
    bf* woh;      cudaGetSymbolAddress((void**)&woh,  g_wout_hi);
    bf* wol;      cudaGetSymbolAddress((void**)&wol,  g_wout_lo);
    bf* ahi;      cudaGetSymbolAddress((void**)&ahi,  g_attn_hi);
    bf* alo;      cudaGetSymbolAddress((void**)&alo,  g_attn_lo);

    // 0) fp32 -> bf16 hi/lo splits
    {
        int n4 = MROWS * DMODEL / 4;
        cvt_kernel<<<(n4 + 255) / 256, 256>>>((const float4*)x, (uint2*)xhi, (uint2*)xlo, n4);
        n4 = DMODEL * QKV_N / 4;
        cvt_kernel<<<(n4 + 255) / 256, 256>>>((const float4*)Wqkv, (uint2*)wqh, (uint2*)wql, n4);
        n4 = DMODEL * DMODEL / 4;
        cvt_kernel<<<(n4 + 255) / 256, 256>>>((const float4*)Wout, (uint2*)woh, (uint2*)wol, n4);
    }
    // 1) QKV projection (tensor cores, bf16x2 split)
    {
        dim3 grid(QKV_N / BN, MROWS / BM);
        mma_gemm<false><<<grid, 256>>>(xhi, xlo, wqh, wql, bqkv, nullptr, qkv,
                                       MROWS, QKV_N, DMODEL);
    }
    // 2) causal flash attention (fp32), emits bf16 hi/lo
    {
        dim3 grid(SLEN / AT, NHEADS, BATCH);
        attn_kernel<<<grid, 64>>>(qkv, ahi, alo);
    }
    // 3) out projection + bias + residual (tensor cores)
    {
        dim3 grid(DMODEL / BN, MROWS / BM);
        mma_gemm<true><<<grid, 256>>>(ahi, alo, woh, wol, bout, x, out,
                                      MROWS, DMODEL, DMODEL);
    }
    // 4) LayerNorm in-place on d_out
    ln_kernel<<<MROWS, 256>>>(out, gamma, beta);
}

// round 3
// speedup vs baseline: 2.2359x; 1.3763x over previous
#include <cuda_runtime.h>
#include <cuda_bf16.h>
#include <cstdint>

#define BATCH 8
#define SLEN 1024
#define DMODEL 1024
#define NHEADS 16
#define HDIM 64
#define MROWS (BATCH * SLEN)       // 8192
#define QKV_N (3 * DMODEL)         // 3072
#define LN_EPS 1e-5f
#define SM_SCALE 0.03125f          // 1/sqrt(1024)

typedef __nv_bfloat16 bf;

// Scratch (static device globals: allocation-free rule)
__device__ bf g_xhi[(size_t)MROWS * DMODEL];
__device__ bf g_xlo[(size_t)MROWS * DMODEL];
__device__ bf g_wqkv_hi[(size_t)DMODEL * QKV_N];
__device__ bf g_wqkv_lo[(size_t)DMODEL * QKV_N];
__device__ bf g_wout_hi[(size_t)DMODEL * DMODEL];
__device__ bf g_wout_lo[(size_t)DMODEL * DMODEL];
__device__ bf g_qkv_hi[(size_t)MROWS * QKV_N];
__device__ bf g_qkv_lo[(size_t)MROWS * QKV_N];
__device__ bf g_attn_hi[(size_t)MROWS * DMODEL];
__device__ bf g_attn_lo[(size_t)MROWS * DMODEL];

// ---------------------------------------------------------------------------
// helpers
// ---------------------------------------------------------------------------
__device__ __forceinline__ uint32_t cvta_smem(const void* p) {
    uint32_t a;
    asm("{.reg .u64 t; cvta.to.shared.u64 t, %1; cvt.u32.u64 %0, t;}"
        : "=r"(a) : "l"(p));
    return a;
}
__device__ __forceinline__ void ldsm4(uint32_t a, uint32_t& r0, uint32_t& r1,
                                      uint32_t& r2, uint32_t& r3) {
    asm volatile("ldmatrix.sync.aligned.m8n8.x4.shared.b16 {%0,%1,%2,%3},[%4];"
                 : "=r"(r0), "=r"(r1), "=r"(r2), "=r"(r3) : "r"(a));
}
__device__ __forceinline__ void ldsm4t(uint32_t a, uint32_t& r0, uint32_t& r1,
                                       uint32_t& r2, uint32_t& r3) {
    asm volatile("ldmatrix.sync.aligned.m8n8.x4.trans.shared.b16 {%0,%1,%2,%3},[%4];"
                 : "=r"(r0), "=r"(r1), "=r"(r2), "=r"(r3) : "r"(a));
}
__device__ __forceinline__ void mma_bf16(float* c, const uint32_t* a,
                                         const uint32_t* b) {
    asm volatile(
        "mma.sync.aligned.m16n8k16.row.col.f32.bf16.bf16.f32 "
        "{%0,%1,%2,%3},{%4,%5,%6,%7},{%8,%9},{%0,%1,%2,%3};"
        : "+f"(c[0]), "+f"(c[1]), "+f"(c[2]), "+f"(c[3])
        : "r"(a[0]), "r"(a[1]), "r"(a[2]), "r"(a[3]), "r"(b[0]), "r"(b[1]));
}
// split two floats into packed bf16x2 hi and lo words
__device__ __forceinline__ void split2(float x, float y, uint32_t& hi,
                                       uint32_t& lo) {
    bf hx = __float2bfloat16(x), hy = __float2bfloat16(y);
    bf lx = __float2bfloat16(x - __bfloat162float(hx));
    bf ly = __float2bfloat16(y - __bfloat162float(hy));
    __nv_bfloat162 h = __halves2bfloat162(hx, hy);
    __nv_bfloat162 l = __halves2bfloat162(lx, ly);
    hi = *(uint32_t*)&h;
    lo = *(uint32_t*)&l;
}

// ---------------------------------------------------------------------------
// fp32 -> (bf16 hi, bf16 lo) split conversion, vectorized by 4
// ---------------------------------------------------------------------------
__global__ __launch_bounds__(256) void cvt_kernel(
    const float4* __restrict__ in, uint2* __restrict__ hi,
    uint2* __restrict__ lo, int n4)
{
    int i = blockIdx.x * blockDim.x + threadIdx.x;
    if (i >= n4) return;
    float4 v = in[i];
    uint2 ho, loo;
    split2(v.x, v.y, ho.x, loo.x);
    split2(v.z, v.w, ho.y, loo.y);
    hi[i] = ho;
    lo[i] = loo;
}

// ---------------------------------------------------------------------------
// Tensor-core GEMM, bf16x2-split inputs. BM=BN=128, BK=32, 8 warps.
// SPLIT=false: fp32 out (+bias,+res). SPLIT=true: bf16 hi/lo out (+bias).
// ---------------------------------------------------------------------------
#define BM 128
#define BN 128
#define BK 32

template <bool RESID, bool SPLIT>
__global__ __launch_bounds__(256, 1) void mma_gemm(
    const bf* __restrict__ Ahi, const bf* __restrict__ Alo,
    const bf* __restrict__ Bhi, const bf* __restrict__ Blo,
    const float* __restrict__ bias, const float* __restrict__ res,
    float* __restrict__ C, bf* __restrict__ Chi, bf* __restrict__ Clo,
    int M, int N, int K)
{
    __shared__ bf Ash[2][BM][BK + 8];
    __shared__ bf Bsh[2][BK][BN + 8];

    const int tid = threadIdx.x;
    const int lane = tid & 31;
    const int warp = tid >> 5;
    const int wm = warp >> 2;
    const int wn = warp & 3;
    const int bm0 = blockIdx.y * BM;
    const int bn0 = blockIdx.x * BN;

    const int ar = tid >> 2;
    const int ac = (tid & 3) * 8;
    const int br = tid >> 3;
    const int bc = (tid & 7) * 16;

    float acc[4][4][4];
    #pragma unroll
    for (int i = 0; i < 4; i++)
        #pragma unroll
        for (int j = 0; j < 4; j++)
            #pragma unroll
            for (int c = 0; c < 4; c++) acc[i][j][c] = 0.0f;

    const bf* Ah = Ahi + (size_t)(bm0 + ar) * K + ac;
    const bf* Al = Alo + (size_t)(bm0 + ar) * K + ac;
    const bf* Bh = Bhi + (size_t)br * N + bn0 + bc;
    const bf* Bl = Blo + (size_t)br * N + bn0 + bc;

    uint4 pa[4], pb[4];
    pa[0] = *(const uint4*)(Ah);
    pa[1] = *(const uint4*)(Ah + (size_t)64 * K);
    pa[2] = *(const uint4*)(Al);
    pa[3] = *(const uint4*)(Al + (size_t)64 * K);
    pb[0] = *(const uint4*)(Bh);
    pb[1] = *(const uint4*)(Bh + 8);
    pb[2] = *(const uint4*)(Bl);
    pb[3] = *(const uint4*)(Bl + 8);

    const int iters = K / BK;
    for (int it = 0; it < iters; it++) {
        {
            uint2* d; const uint2* s;
            d = (uint2*)&Ash[0][ar][ac];      s = (const uint2*)&pa[0]; d[0]=s[0]; d[1]=s[1];
            d = (uint2*)&Ash[0][ar+64][ac];   s = (const uint2*)&pa[1]; d[0]=s[0]; d[1]=s[1];
            d = (uint2*)&Ash[1][ar][ac];      s = (const uint2*)&pa[2]; d[0]=s[0]; d[1]=s[1];
            d = (uint2*)&Ash[1][ar+64][ac];   s = (const uint2*)&pa[3]; d[0]=s[0]; d[1]=s[1];
            d = (uint2*)&Bsh[0][br][bc];      s = (const uint2*)&pb[0]; d[0]=s[0]; d[1]=s[1];
            d = (uint2*)&Bsh[0][br][bc+8];    s = (const uint2*)&pb[1]; d[0]=s[0]; d[1]=s[1];
            d = (uint2*)&Bsh[1][br][bc];      s = (const uint2*)&pb[2]; d[0]=s[0]; d[1]=s[1];
            d = (uint2*)&Bsh[1][br][bc+8];    s = (const uint2*)&pb[3]; d[0]=s[0]; d[1]=s[1];
        }
        __syncthreads();

        if (it + 1 < iters) {
            const size_t ka = (size_t)(it + 1) * BK;
            pa[0] = *(const uint4*)(Ah + ka);
            pa[1] = *(const uint4*)(Ah + (size_t)64 * K + ka);
            pa[2] = *(const uint4*)(Al + ka);
            pa[3] = *(const uint4*)(Al + (size_t)64 * K + ka);
            const size_t kb = ka * N;
            pb[0] = *(const uint4*)(Bh + kb);
            pb[1] = *(const uint4*)(Bh + kb + 8);
            pb[2] = *(const uint4*)(Bl + kb);
            pb[3] = *(const uint4*)(Bl + kb + 8);
        }

        #pragma unroll
        for (int kk = 0; kk < 2; kk++) {
            uint32_t ah[4][4], al[4][4], bh[4][2], bl[4][2];
            const int arow = wm * 64 + (lane & 15);
            const int acol = kk * 16 + (lane >> 4) * 8;
            #pragma unroll
            for (int mt = 0; mt < 4; mt++) {
                ldsm4(cvta_smem(&Ash[0][arow + mt * 16][acol]),
                      ah[mt][0], ah[mt][1], ah[mt][2], ah[mt][3]);
                ldsm4(cvta_smem(&Ash[1][arow + mt * 16][acol]),
                      al[mt][0], al[mt][1], al[mt][2], al[mt][3]);
            }
            const int brow = kk * 16 + (lane & 15);
            #pragma unroll
            for (int ng = 0; ng < 2; ng++) {
                const int bcol = wn * 32 + ng * 16 + (lane >> 4) * 8;
                ldsm4t(cvta_smem(&Bsh[0][brow][bcol]),
                       bh[2*ng][0], bh[2*ng][1], bh[2*ng+1][0], bh[2*ng+1][1]);
                ldsm4t(cvta_smem(&Bsh[1][brow][bcol]),
                       bl[2*ng][0], bl[2*ng][1], bl[2*ng+1][0], bl[2*ng+1][1]);
            }
            #pragma unroll
            for (int mt = 0; mt < 4; mt++)
                #pragma unroll
                for (int nt = 0; nt < 4; nt++) {
                    mma_bf16(acc[mt][nt], ah[mt], bh[nt]);
                    mma_bf16(acc[mt][nt], ah[mt], bl[nt]);
                    mma_bf16(acc[mt][nt], al[mt], bh[nt]);
                }
        }
        __syncthreads();
    }

    const int r0 = lane >> 2;
    const int cp = (lane & 3) * 2;
    #pragma unroll
    for (int mt = 0; mt < 4; mt++) {
        #pragma unroll
        for (int nt = 0; nt < 4; nt++) {
            const int gc = bn0 + wn * 32 + nt * 8 + cp;
            const float2 bv = *(const float2*)(bias + gc);
            #pragma unroll
            for (int h = 0; h < 2; h++) {
                const int gr = bm0 + wm * 64 + mt * 16 + r0 + h * 8;
                float ox = acc[mt][nt][2 * h + 0] + bv.x;
                float oy = acc[mt][nt][2 * h + 1] + bv.y;
                if (SPLIT) {
                    uint32_t hi, lo;
                    split2(ox, oy, hi, lo);
                    *(uint32_t*)(Chi + (size_t)gr * N + gc) = hi;
                    *(uint32_t*)(Clo + (size_t)gr * N + gc) = lo;
                } else {
                    if (RESID) {
                        float2 rv = *(const float2*)(res + (size_t)gr * N + gc);
                        ox += rv.x; oy += rv.y;
                    }
                    float2 o; o.x = ox; o.y = oy;
                    *(float2*)(C + (size_t)gr * N + gc) = o;
                }
            }
        }
    }
}

// ---------------------------------------------------------------------------
// Tensor-core causal flash attention.
// Grid (S/128, H, B), 256 thr (8 warps), each warp owns 16 query rows.
// QK^T and PV on HMMA with 3-term bf16 split; fp32 online softmax.
// Consumes split QKV (g_qkv_hi/lo), emits split attn output.
// ---------------------------------------------------------------------------
#define QTILE 128
#define KTILE 64
#define SROW 72   // padded smem row length (bf16 elems)

__global__ __launch_bounds__(256, 1) void attn_mma(
    const bf* __restrict__ qkv_hi, const bf* __restrict__ qkv_lo,
    bf* __restrict__ out_hi, bf* __restrict__ out_lo)
{
    __shared__ __align__(16) bf sbuf[2 * QTILE * SROW];  // 36,864 B

    bf* sQh = sbuf;
    bf* sQl = sbuf + QTILE * SROW;
    bf* sKh = sbuf;
    bf* sKl = sbuf + KTILE * SROW;
    bf* sVh = sbuf + 2 * KTILE * SROW;
    bf* sVl = sbuf + 3 * KTILE * SROW;

    const int tid  = threadIdx.x;
    const int lane = tid & 31;
    const int warp = tid >> 5;
    const int qt = blockIdx.x;
    const int h  = blockIdx.y;
    const int bz = blockIdx.z;

    const size_t rowstride = QKV_N;
    const size_t batch_row = (size_t)bz * SLEN;

    // ---- stage Q tile (128 x 64) hi/lo into smem ----
    for (int i = tid; i < QTILE * 16; i += 256) {
        const int r = i >> 4;
        const int c = (i & 15) * 4;
        const size_t g = (batch_row + qt * QTILE + r) * rowstride + h * HDIM + c;
        *(uint2*)&sQh[r * SROW + c] = *(const uint2*)(qkv_hi + g);
        *(uint2*)&sQl[r * SROW + c] = *(const uint2*)(qkv_lo + g);
    }
    __syncthreads();

    // ---- load Q fragments (A-frag, 4 k-steps) ----
    uint32_t qh[4][4], ql[4][4];
    {
        const int arow = warp * 16 + (lane & 15);
        #pragma unroll
        for (int ks = 0; ks < 4; ks++) {
            const int acol = ks * 16 + (lane >> 4) * 8;
            ldsm4(cvta_smem(&sQh[arow * SROW + acol]),
                  qh[ks][0], qh[ks][1], qh[ks][2], qh[ks][3]);
            ldsm4(cvta_smem(&sQl[arow * SROW + acol]),
                  ql[ks][0], ql[ks][1], ql[ks][2], ql[ks][3]);
        }
    }
    __syncthreads();   // before K/V overwrite sbuf

    const int base = qt * QTILE + warp * 16;       // warp's first query row
    const int ktmax_warp = 2 * qt + (warp >= 4 ? 1 : 0);
    const int nkt = 2 * qt + 2;                    // tiles staged by block

    float o[8][4];
    #pragma unroll
    for (int nt = 0; nt < 8; nt++)
        #pragma unroll
        for (int e = 0; e < 4; e++) o[nt][e] = 0.0f;
    float m_a = -1e30f, m_b = -1e30f, l_a = 0.0f, l_b = 0.0f;

    for (int kt = 0; kt < nkt; kt++) {
        // ---- stage K/V tile (64 x 64 each) hi/lo ----
        for (int i = tid; i < KTILE * 16; i += 256) {
            const int r = i >> 4;
            const int c = (i & 15) * 4;
            const size_t gk = (batch_row + kt * KTILE + r) * rowstride
                              + DMODEL + h * HDIM + c;
            *(uint2*)&sKh[r * SROW + c] = *(const uint2*)(qkv_hi + gk);
            *(uint2*)&sKl[r * SROW + c] = *(const uint2*)(qkv_lo + gk);
            *(uint2*)&sVh[r * SROW + c] = *(const uint2*)(qkv_hi + gk + DMODEL);
            *(uint2*)&sVl[r * SROW + c] = *(const uint2*)(qkv_lo + gk + DMODEL);
        }
        __syncthreads();

        if (kt <= ktmax_warp) {
            // ---- S = Q K^T (3-term split) ----
            float s[8][4];
            #pragma unroll
            for (int nt = 0; nt < 8; nt++)
                #pragma unroll
                for (int e = 0; e < 4; e++) s[nt][e] = 0.0f;

            #pragma unroll
            for (int ks = 0; ks < 4; ks++) {
                #pragma unroll
                for (int np = 0; np < 4; np++) {
                    uint32_t kh0, kh1, kh2, kh3, kl0, kl1, kl2, kl3;
                    const int addr = (np * 16 + (lane & 15)) * SROW
                                     + ks * 16 + (lane >> 4) * 8;
                    ldsm4(cvta_smem(&sKh[addr]), kh0, kh1, kh2, kh3);
                    ldsm4(cvta_smem(&sKl[addr]), kl0, kl1, kl2, kl3);
                    uint32_t beh[2] = {kh0, kh2}, boh[2] = {kh1, kh3};
                    uint32_t bel[2] = {kl0, kl2}, bol[2] = {kl1, kl3};
                    mma_bf16(s[2*np],   qh[ks], beh);
                    mma_bf16(s[2*np],   qh[ks], bel);
                    mma_bf16(s[2*np],   ql[ks], beh);
                    mma_bf16(s[2*np+1], qh[ks], boh);
                    mma_bf16(s[2*np+1], qh[ks], bol);
                    mma_bf16(s[2*np+1], ql[ks], boh);
                }
            }

            // ---- causal mask ----
            if (kt * KTILE + 63 > base) {
                const int ra = base + (lane >> 2);
                #pragma unroll
                for (int nt = 0; nt < 8; nt++) {
                    const int kc = kt * KTILE + nt * 8 + (lane & 3) * 2;
                    if (kc > ra)      s[nt][0] = -1e30f;
                    if (kc + 1 > ra)  s[nt][1] = -1e30f;
                    if (kc > ra + 8)     s[nt][2] = -1e30f;
                    if (kc + 1 > ra + 8) s[nt][3] = -1e30f;
                }
            }

            // ---- online softmax ----
            float ta = -1e30f, tb = -1e30f;
            #pragma unroll
            for (int nt = 0; nt < 8; nt++) {
                ta = fmaxf(ta, fmaxf(s[nt][0], s[nt][1]));
                tb = fmaxf(tb, fmaxf(s[nt][2], s[nt][3]));
            }
            ta = fmaxf(ta, __shfl_xor_sync(0xffffffffu, ta, 1));
            ta = fmaxf(ta, __shfl_xor_sync(0xffffffffu, ta, 2));
            tb = fmaxf(tb, __shfl_xor_sync(0xffffffffu, tb, 1));
            tb = fmaxf(tb, __shfl_xor_sync(0xffffffffu, tb, 2));

            const float mna = fmaxf(m_a, ta);
            const float mnb = fmaxf(m_b, tb);
            const float ca = __expf((m_a - mna) * SM_SCALE);
            const float cb = __expf((m_b - mnb) * SM_SCALE);
            m_a = mna; m_b = mnb;
            l_a *= ca; l_b *= cb;
            #pragma unroll
            for (int nt = 0; nt < 8; nt++) {
                o[nt][0] *= ca; o[nt][1] *= ca;
                o[nt][2] *= cb; o[nt][3] *= cb;
            }

            float sa = 0.0f, sb = 0.0f;
            #pragma unroll
            for (int nt = 0; nt < 8; nt++) {
                float p0 = __expf((s[nt][0] - mna) * SM_SCALE);
                float p1 = __expf((s[nt][1] - mna) * SM_SCALE);
                float p2 = __expf((s[nt][2] - mnb) * SM_SCALE);
                float p3 = __expf((s[nt][3] - mnb) * SM_SCALE);
                s[nt][0] = p0; s[nt][1] = p1; s[nt][2] = p2; s[nt][3] = p3;
                sa += p0 + p1; sb += p2 + p3;
            }
            sa += __shfl_xor_sync(0xffffffffu, sa, 1);
            sa += __shfl_xor_sync(0xffffffffu, sa, 2);
            sb += __shfl_xor_sync(0xffffffffu, sb, 1);
            sb += __shfl_xor_sync(0xffffffffu, sb, 2);
            l_a += sa; l_b += sb;

            // ---- O += P V (3-term split) ----
            #pragma unroll
            for (int ks = 0; ks < 4; ks++) {
                uint32_t pah[4], pal[4];
                split2(s[2*ks][0],   s[2*ks][1],   pah[0], pal[0]);
                split2(s[2*ks][2],   s[2*ks][3],   pah[1], pal[1]);
                split2(s[2*ks+1][0], s[2*ks+1][1], pah[2], pal[2]);
                split2(s[2*ks+1][2], s[2*ks+1][3], pah[3], pal[3]);
                #pragma unroll
                for (int np = 0; np < 4; np++) {
                    uint32_t vh0, vh1, vh2, vh3, vl0, vl1, vl2, vl3;
                    const int addr = (ks * 16 + (lane & 15)) * SROW
                                     + np * 16 + (lane >> 4) * 8;
                    ldsm4t(cvta_smem(&sVh[addr]), vh0, vh1, vh2, vh3);
                    ldsm4t(cvta_smem(&sVl[addr]), vl0, vl1, vl2, vl3);
                    uint32_t veh[2] = {vh0, vh1}, voh[2] = {vh2, vh3};
                    uint32_t vel[2] = {vl0, vl1}, vol[2] = {vl2, vl3};
                    mma_bf16(o[2*np],   pah, veh);
                    mma_bf16(o[2*np],   pah, vel);
                    mma_bf16(o[2*np],   pal, veh);
                    mma_bf16(o[2*np+1], pah, voh);
                    mma_bf16(o[2*np+1], pah, vol);
                    mma_bf16(o[2*np+1], pal, voh);
                }
            }
        }
        __syncthreads();
    }

    // ---- epilogue: normalize, split to bf16 hi/lo, store ----
    const float ia = 1.0f / l_a;
    const float ib = 1.0f / l_b;
    const int ra = base + (lane >> 2);
    const size_t rowa = (batch_row + ra) * (size_t)DMODEL + h * HDIM;
    const size_t rowb = rowa + 8 * DMODEL;
    #pragma unroll
    for (int nt = 0; nt < 8; nt++) {
        const int col = nt * 8 + (lane & 3) * 2;
        uint32_t hi, lo;
        split2(o[nt][0] * ia, o[nt][1] * ia, hi, lo);
        *(uint32_t*)(out_hi + rowa + col) = hi;
        *(uint32_t*)(out_lo + rowa + col) = lo;
        split2(o[nt][2] * ib, o[nt][3] * ib, hi, lo);
        *(uint32_t*)(out_hi + rowb + col) = hi;
        *(uint32_t*)(out_lo + rowb + col) = lo;
    }
}

// ---------------------------------------------------------------------------
// LayerNorm over last dim, in-place. One block (256 thr) per row of 1024.
// ---------------------------------------------------------------------------
__global__ __launch_bounds__(256) void ln_kernel(
    float* __restrict__ io, const float* __restrict__ gamma,
    const float* __restrict__ beta)
{
    const int row = blockIdx.x;
    const int tid = threadIdx.x;
    float4* p = (float4*)(io + (size_t)row * DMODEL);
    float4 v = p[tid];

    float s  = v.x + v.y + v.z + v.w;
    float s2 = fmaf(v.x, v.x, fmaf(v.y, v.y, fmaf(v.z, v.z, v.w * v.w)));

    #pragma unroll
    for (int ofs = 16; ofs; ofs >>= 1) {
        s  += __shfl_xor_sync(0xffffffffu, s, ofs);
        s2 += __shfl_xor_sync(0xffffffffu, s2, ofs);
    }
    __shared__ float shs[8], shs2[8];
    const int w = tid >> 5, l = tid & 31;
    if (l == 0) { shs[w] = s; shs2[w] = s2; }
    __syncthreads();
    if (tid < 32) {
        float a  = (l < 8) ? shs[l]  : 0.0f;
        float a2 = (l < 8) ? shs2[l] : 0.0f;
        #pragma unroll
        for (int ofs = 4; ofs; ofs >>= 1) {
            a  += __shfl_xor_sync(0xffffffffu, a, ofs);
            a2 += __shfl_xor_sync(0xffffffffu, a2, ofs);
        }
        if (l == 0) { shs[0] = a; shs2[0] = a2; }
    }
    __syncthreads();

    const float mean = shs[0] * (1.0f / DMODEL);
    const float var  = shs2[0] * (1.0f / DMODEL) - mean * mean;
    const float rstd = rsqrtf(var + LN_EPS);

    float4 g  = ((const float4*)gamma)[tid];
    float4 be = ((const float4*)beta)[tid];
    float4 r;
    r.x = (v.x - mean) * rstd * g.x + be.x;
    r.y = (v.y - mean) * rstd * g.y + be.y;
    r.z = (v.z - mean) * rstd * g.z + be.z;
    r.w = (v.w - mean) * rstd * g.w + be.w;
    p[tid] = r;
}

// ---------------------------------------------------------------------------
extern "C" void kernel_launch(void* const* d_in, const int* in_sizes, int n_in,
                              void* d_out, int out_size)
{
    const float* x     = (const float*)d_in[0];
    const float* Wqkv  = (const float*)d_in[1];
    const float* bqkv  = (const float*)d_in[2];
    const float* Wout  = (const float*)d_in[3];
    const float* bout  = (const float*)d_in[4];
    const float* gamma = (const float*)d_in[5];
    const float* beta  = (const float*)d_in[6];
    float* out = (float*)d_out;

    bf *xhi, *xlo, *wqh, *wql, *woh, *wol, *qh, *qlo, *ahi, *alo;
    cudaGetSymbolAddress((void**)&xhi, g_xhi);
    cudaGetSymbolAddress((void**)&xlo, g_xlo);
    cudaGetSymbolAddress((void**)&wqh, g_wqkv_hi);
    cudaGetSymbolAddress((void**)&wql, g_wqkv_lo);
    cudaGetSymbolAddress((void**)&woh, g_wout_hi);
    cudaGetSymbolAddress((void**)&wol, g_wout_lo);
    cudaGetSymbolAddress((void**)&qh,  g_qkv_hi);
    cudaGetSymbolAddress((void**)&qlo, g_qkv_lo);
    cudaGetSymbolAddress((void**)&ahi, g_attn_hi);
    cudaGetSymbolAddress((void**)&alo, g_attn_lo);

    // 0) fp32 -> bf16 hi/lo splits of inputs
    {
        int n4 = MROWS * DMODEL / 4;
        cvt_kernel<<<(n4 + 255) / 256, 256>>>((const float4*)x, (uint2*)xhi, (uint2*)xlo, n4);
        n4 = DMODEL * QKV_N / 4;
        cvt_kernel<<<(n4 + 255) / 256, 256>>>((const float4*)Wqkv, (uint2*)wqh, (uint2*)wql, n4);
        n4 = DMODEL * DMODEL / 4;
        cvt_kernel<<<(n4 + 255) / 256, 256>>>((const float4*)Wout, (uint2*)woh, (uint2*)wol, n4);
    }
    // 1) QKV projection -> split bf16 output
    {
        dim3 grid(QKV_N / BN, MROWS / BM);
        mma_gemm<false, true><<<grid, 256>>>(xhi, xlo, wqh, wql, bqkv, nullptr,
                                             nullptr, qh, qlo,
                                             MROWS, QKV_N, DMODEL);
    }
    // 2) tensor-core causal flash attention -> split bf16 output
    {
        dim3 grid(SLEN / QTILE, NHEADS, BATCH);
        attn_mma<<<grid, 256>>>(qh, qlo, ahi, alo);
    }
    // 3) out projection + bias + residual -> fp32
    {
        dim3 grid(DMODEL / BN, MROWS / BM);
        mma_gemm<true, false><<<grid, 256>>>(ahi, alo, woh, wol, bout, x,
                                             out, nullptr, nullptr,
                                             MROWS, DMODEL, DMODEL);
    }
    // 4) LayerNorm in-place on d_out
    ln_kernel<<<MROWS, 256>>>(out, gamma, beta);
}

// round 5
// speedup vs baseline: 2.7554x; 1.2324x over previous
#include <cuda_runtime.h>
#include <cuda_bf16.h>
#include <cstdint>

#define BATCH 8
#define SLEN 1024
#define DMODEL 1024
#define NHEADS 16
#define HDIM 64
#define MROWS (BATCH * SLEN)       // 8192
#define QKV_N (3 * DMODEL)         // 3072
#define LN_EPS 1e-5f
#define SM_SCALE 0.03125f          // 1/sqrt(1024)

typedef __nv_bfloat16 bf;

// Scratch (static device globals: allocation-free rule)
__device__ bf g_xhi[(size_t)MROWS * DMODEL];
__device__ bf g_xlo[(size_t)MROWS * DMODEL];
__device__ bf g_wqkv_hi[(size_t)DMODEL * QKV_N];
__device__ bf g_wqkv_lo[(size_t)DMODEL * QKV_N];
__device__ bf g_wout_hi[(size_t)DMODEL * DMODEL];
__device__ bf g_wout_lo[(size_t)DMODEL * DMODEL];
__device__ bf g_qkv_hi[(size_t)MROWS * QKV_N];
__device__ bf g_qkv_lo[(size_t)MROWS * QKV_N];
__device__ bf g_attn_hi[(size_t)MROWS * DMODEL];
__device__ bf g_attn_lo[(size_t)MROWS * DMODEL];

// ---------------------------------------------------------------------------
// helpers
// ---------------------------------------------------------------------------
__device__ __forceinline__ uint32_t cvta_smem(const void* p) {
    uint32_t a;
    asm("{.reg .u64 t; cvta.to.shared.u64 t, %1; cvt.u32.u64 %0, t;}"
        : "=r"(a) : "l"(p));
    return a;
}
__device__ __forceinline__ void ldsm4(uint32_t a, uint32_t& r0, uint32_t& r1,
                                      uint32_t& r2, uint32_t& r3) {
    asm volatile("ldmatrix.sync.aligned.m8n8.x4.shared.b16 {%0,%1,%2,%3},[%4];"
                 : "=r"(r0), "=r"(r1), "=r"(r2), "=r"(r3) : "r"(a));
}
__device__ __forceinline__ void ldsm4t(uint32_t a, uint32_t& r0, uint32_t& r1,
                                       uint32_t& r2, uint32_t& r3) {
    asm volatile("ldmatrix.sync.aligned.m8n8.x4.trans.shared.b16 {%0,%1,%2,%3},[%4];"
                 : "=r"(r0), "=r"(r1), "=r"(r2), "=r"(r3) : "r"(a));
}
__device__ __forceinline__ void mma_bf16(float* c, const uint32_t* a,
                                         const uint32_t* b) {
    asm volatile(
        "mma.sync.aligned.m16n8k16.row.col.f32.bf16.bf16.f32 "
        "{%0,%1,%2,%3},{%4,%5,%6,%7},{%8,%9},{%0,%1,%2,%3};"
        : "+f"(c[0]), "+f"(c[1]), "+f"(c[2]), "+f"(c[3])
        : "r"(a[0]), "r"(a[1]), "r"(a[2]), "r"(a[3]), "r"(b[0]), "r"(b[1]));
}
__device__ __forceinline__ void split2(float x, float y, uint32_t& hi,
                                       uint32_t& lo) {
    bf hx = __float2bfloat16(x), hy = __float2bfloat16(y);
    bf lx = __float2bfloat16(x - __bfloat162float(hx));
    bf ly = __float2bfloat16(y - __bfloat162float(hy));
    __nv_bfloat162 h = __halves2bfloat162(hx, hy);
    __nv_bfloat162 l = __halves2bfloat162(lx, ly);
    hi = *(uint32_t*)&h;
    lo = *(uint32_t*)&l;
}

// ---------------------------------------------------------------------------
// fp32 -> (bf16 hi, bf16 lo) split conversion, vectorized by 4
// ---------------------------------------------------------------------------
__global__ __launch_bounds__(256) void cvt_kernel(
    const float4* __restrict__ in, uint2* __restrict__ hi,
    uint2* __restrict__ lo, int n4)
{
    int i = blockIdx.x * blockDim.x + threadIdx.x;
    if (i >= n4) return;
    float4 v = in[i];
    uint2 ho, loo;
    split2(v.x, v.y, ho.x, loo.x);
    split2(v.z, v.w, ho.y, loo.y);
    hi[i] = ho;
    lo[i] = loo;
}

// ---------------------------------------------------------------------------
// Tensor-core GEMM, bf16x2-split inputs, DOUBLE-BUFFERED smem (1 sync/iter).
// BM=BN=128, BK=32, 8 warps (64x32 warp tiles).
// ---------------------------------------------------------------------------
#define BM 128
#define BN 128
#define BK 32
#define A_STR 40        // BK + 8 pad
#define B_STR 136       // BN + 8 pad
#define ABUF (BM * A_STR)               // 5120 elems per hi/lo
#define BBUF (BK * B_STR)               // 4352 elems per hi/lo
#define GBUF_ELEMS (2 * ABUF + 2 * BBUF)  // 18944 elems = 37,888 B / buffer
#define GSMEM_BYTES (2 * GBUF_ELEMS * 2)  // 75,776 B

template <bool RESID, bool SPLIT>
__global__ __launch_bounds__(256, 1) void mma_gemm(
    const bf* __restrict__ Ahi, const bf* __restrict__ Alo,
    const bf* __restrict__ Bhi, const bf* __restrict__ Blo,
    const float* __restrict__ bias, const float* __restrict__ res,
    float* __restrict__ C, bf* __restrict__ Chi, bf* __restrict__ Clo,
    int M, int N, int K)
{
    extern __shared__ __align__(16) bf dsm[];

    const int tid = threadIdx.x;
    const int lane = tid & 31;
    const int warp = tid >> 5;
    const int wm = warp >> 2;
    const int wn = warp & 3;
    const int bm0 = blockIdx.y * BM;
    const int bn0 = blockIdx.x * BN;

    const int ar = tid >> 2;          // 0..63 (rows ar, ar+64)
    const int ac = (tid & 3) * 8;     // k offset
    const int br = tid >> 3;          // 0..31
    const int bc = (tid & 7) * 16;    // n offset

    float acc[4][4][4];
    #pragma unroll
    for (int i = 0; i < 4; i++)
        #pragma unroll
        for (int j = 0; j < 4; j++)
            #pragma unroll
            for (int c = 0; c < 4; c++) acc[i][j][c] = 0.0f;

    const bf* Ah = Ahi + (size_t)(bm0 + ar) * K + ac;
    const bf* Al = Alo + (size_t)(bm0 + ar) * K + ac;
    const bf* Bh = Bhi + (size_t)br * N + bn0 + bc;
    const bf* Bl = Blo + (size_t)br * N + bn0 + bc;

    uint4 pa[4], pb[4];
    pa[0] = *(const uint4*)(Ah);
    pa[1] = *(const uint4*)(Ah + (size_t)64 * K);
    pa[2] = *(const uint4*)(Al);
    pa[3] = *(const uint4*)(Al + (size_t)64 * K);
    pb[0] = *(const uint4*)(Bh);
    pb[1] = *(const uint4*)(Bh + 8);
    pb[2] = *(const uint4*)(Bl);
    pb[3] = *(const uint4*)(Bl + 8);

    const int iters = K / BK;
    for (int it = 0; it < iters; it++) {
        bf* buf = dsm + (it & 1) * GBUF_ELEMS;
        bf* sAh = buf;
        bf* sAl = buf + ABUF;
        bf* sBh = buf + 2 * ABUF;
        bf* sBl = buf + 2 * ABUF + BBUF;
        {   // stage prefetched tile
            uint2* d; const uint2* s;
            d = (uint2*)&sAh[ar * A_STR + ac];        s = (const uint2*)&pa[0]; d[0]=s[0]; d[1]=s[1];
            d = (uint2*)&sAh[(ar + 64) * A_STR + ac]; s = (const uint2*)&pa[1]; d[0]=s[0]; d[1]=s[1];
            d = (uint2*)&sAl[ar * A_STR + ac];        s = (const uint2*)&pa[2]; d[0]=s[0]; d[1]=s[1];
            d = (uint2*)&sAl[(ar + 64) * A_STR + ac]; s = (const uint2*)&pa[3]; d[0]=s[0]; d[1]=s[1];
            d = (uint2*)&sBh[br * B_STR + bc];        s = (const uint2*)&pb[0]; d[0]=s[0]; d[1]=s[1];
            d = (uint2*)&sBh[br * B_STR + bc + 8];    s = (const uint2*)&pb[1]; d[0]=s[0]; d[1]=s[1];
            d = (uint2*)&sBl[br * B_STR + bc];        s = (const uint2*)&pb[2]; d[0]=s[0]; d[1]=s[1];
            d = (uint2*)&sBl[br * B_STR + bc + 8];    s = (const uint2*)&pb[3]; d[0]=s[0]; d[1]=s[1];
        }
        __syncthreads();

        if (it + 1 < iters) {   // prefetch next tile (overlaps with MMAs)
            const size_t ka = (size_t)(it + 1) * BK;
            pa[0] = *(const uint4*)(Ah + ka);
            pa[1] = *(const uint4*)(Ah + (size_t)64 * K + ka);
            pa[2] = *(const uint4*)(Al + ka);
            pa[3] = *(const uint4*)(Al + (size_t)64 * K + ka);
            const size_t kb = ka * N;
            pb[0] = *(const uint4*)(Bh + kb);
            pb[1] = *(const uint4*)(Bh + kb + 8);
            pb[2] = *(const uint4*)(Bl + kb);
            pb[3] = *(const uint4*)(Bl + kb + 8);
        }

        #pragma unroll
        for (int kk = 0; kk < 2; kk++) {
            uint32_t ah[4][4], al[4][4], bh[4][2], bl[4][2];
            const int arow = wm * 64 + (lane & 15);
            const int acol = kk * 16 + (lane >> 4) * 8;
            #pragma unroll
            for (int mt = 0; mt < 4; mt++) {
                ldsm4(cvta_smem(&sAh[(arow + mt * 16) * A_STR + acol]),
                      ah[mt][0], ah[mt][1], ah[mt][2], ah[mt][3]);
                ldsm4(cvta_smem(&sAl[(arow + mt * 16) * A_STR + acol]),
                      al[mt][0], al[mt][1], al[mt][2], al[mt][3]);
            }
            const int brow = kk * 16 + (lane & 15);
            #pragma unroll
            for (int ng = 0; ng < 2; ng++) {
                const int bcol = wn * 32 + ng * 16 + (lane >> 4) * 8;
                ldsm4t(cvta_smem(&sBh[brow * B_STR + bcol]),
                       bh[2*ng][0], bh[2*ng][1], bh[2*ng+1][0], bh[2*ng+1][1]);
                ldsm4t(cvta_smem(&sBl[brow * B_STR + bcol]),
                       bl[2*ng][0], bl[2*ng][1], bl[2*ng+1][0], bl[2*ng+1][1]);
            }
            #pragma unroll
            for (int mt = 0; mt < 4; mt++)
                #pragma unroll
                for (int nt = 0; nt < 4; nt++) {
                    mma_bf16(acc[mt][nt], ah[mt], bh[nt]);
                    mma_bf16(acc[mt][nt], ah[mt], bl[nt]);
                    mma_bf16(acc[mt][nt], al[mt], bh[nt]);
                }
        }
        // no trailing sync: next iter stores to the other buffer; the sync at
        // the top of it+1 orders those stores against this iter's reads.
    }

    const int r0 = lane >> 2;
    const int cp = (lane & 3) * 2;
    #pragma unroll
    for (int mt = 0; mt < 4; mt++) {
        #pragma unroll
        for (int nt = 0; nt < 4; nt++) {
            const int gc = bn0 + wn * 32 + nt * 8 + cp;
            const float2 bv = *(const float2*)(bias + gc);
            #pragma unroll
            for (int h = 0; h < 2; h++) {
                const int gr = bm0 + wm * 64 + mt * 16 + r0 + h * 8;
                float ox = acc[mt][nt][2 * h + 0] + bv.x;
                float oy = acc[mt][nt][2 * h + 1] + bv.y;
                if (SPLIT) {
                    uint32_t hi, lo;
                    split2(ox, oy, hi, lo);
                    *(uint32_t*)(Chi + (size_t)gr * N + gc) = hi;
                    *(uint32_t*)(Clo + (size_t)gr * N + gc) = lo;
                } else {
                    if (RESID) {
                        float2 rv = *(const float2*)(res + (size_t)gr * N + gc);
                        ox += rv.x; oy += rv.y;
                    }
                    float2 o; o.x = ox; o.y = oy;
                    *(float2*)(C + (size_t)gr * N + gc) = o;
                }
            }
        }
    }
}

// ---------------------------------------------------------------------------
// Tensor-core causal flash attention, DOUBLE-BUFFERED K/V (1 sync/iter).
// Grid (S/128, H, B), 256 thr (8 warps), each warp owns 16 query rows.
// ---------------------------------------------------------------------------
#define QTILE 128
#define KTILE 64
#define SROW 72
#define KVBUF (4 * KTILE * SROW)         // 18,432 elems = 36,864 B / buffer
#define ASMEM_BYTES (2 * KVBUF * 2)      // 73,728 B

__global__ __launch_bounds__(256, 1) void attn_mma(
    const bf* __restrict__ qkv_hi, const bf* __restrict__ qkv_lo,
    bf* __restrict__ out_hi, bf* __restrict__ out_lo)
{
    extern __shared__ __align__(16) bf dsm[];

    const int tid  = threadIdx.x;
    const int lane = tid & 31;
    const int warp = tid >> 5;
    const int qt = blockIdx.x;
    const int h  = blockIdx.y;
    const int bz = blockIdx.z;

    const size_t rowstride = QKV_N;
    const size_t batch_row = (size_t)bz * SLEN;

    // ---- stage Q tile into buffer 0 region, grab fragments ----
    {
        bf* sQh = dsm;
        bf* sQl = dsm + QTILE * SROW;
        for (int i = tid; i < QTILE * 16; i += 256) {
            const int r = i >> 4;
            const int c = (i & 15) * 4;
            const size_t g = (batch_row + qt * QTILE + r) * rowstride + h * HDIM + c;
            *(uint2*)&sQh[r * SROW + c] = *(const uint2*)(qkv_hi + g);
            *(uint2*)&sQl[r * SROW + c] = *(const uint2*)(qkv_lo + g);
        }
    }
    __syncthreads();

    uint32_t qh[4][4], ql[4][4];
    {
        bf* sQh = dsm;
        bf* sQl = dsm + QTILE * SROW;
        const int arow = warp * 16 + (lane & 15);
        #pragma unroll
        for (int ks = 0; ks < 4; ks++) {
            const int acol = ks * 16 + (lane >> 4) * 8;
            ldsm4(cvta_smem(&sQh[arow * SROW + acol]),
                  qh[ks][0], qh[ks][1], qh[ks][2], qh[ks][3]);
            ldsm4(cvta_smem(&sQl[arow * SROW + acol]),
                  ql[ks][0], ql[ks][1], ql[ks][2], ql[ks][3]);
        }
    }
    __syncthreads();   // before K/V staging overwrites the Q region

    const int base = qt * QTILE + warp * 16;
    const int ktmax_warp = 2 * qt + (warp >= 4 ? 1 : 0);
    const int nkt = 2 * qt + 2;

    // prefetch registers for K/V tile (4 items/thread x 4 arrays)
    uint2 pkh[4], pkl[4], pvh[4], pvl[4];
    int pr[4], pc[4];
    #pragma unroll
    for (int j = 0; j < 4; j++) {
        const int i = tid + j * 256;
        pr[j] = i >> 4;
        pc[j] = (i & 15) * 4;
    }

    auto prefetch = [&](int kt) {
        #pragma unroll
        for (int j = 0; j < 4; j++) {
            const size_t gk = (batch_row + kt * KTILE + pr[j]) * rowstride
                              + DMODEL + h * HDIM + pc[j];
            pkh[j] = *(const uint2*)(qkv_hi + gk);
            pkl[j] = *(const uint2*)(qkv_lo + gk);
            pvh[j] = *(const uint2*)(qkv_hi + gk + DMODEL);
            pvl[j] = *(const uint2*)(qkv_lo + gk + DMODEL);
        }
    };
    auto stash = [&](bf* b) {
        bf* sKh = b;
        bf* sKl = b + KTILE * SROW;
        bf* sVh = b + 2 * KTILE * SROW;
        bf* sVl = b + 3 * KTILE * SROW;
        #pragma unroll
        for (int j = 0; j < 4; j++) {
            const int o = pr[j] * SROW + pc[j];
            *(uint2*)&sKh[o] = pkh[j];
            *(uint2*)&sKl[o] = pkl[j];
            *(uint2*)&sVh[o] = pvh[j];
            *(uint2*)&sVl[o] = pvl[j];
        }
    };

    float o[8][4];
    #pragma unroll
    for (int nt = 0; nt < 8; nt++)
        #pragma unroll
        for (int e = 0; e < 4; e++) o[nt][e] = 0.0f;
    float m_a = -1e30f, m_b = -1e30f, l_a = 0.0f, l_b = 0.0f;

    // prologue: stage tile 0
    prefetch(0);
    stash(dsm);
    __syncthreads();

    for (int kt = 0; kt < nkt; kt++) {
        bf* buf = dsm + (kt & 1) * KVBUF;
        bf* sKh = buf;
        bf* sKl = buf + KTILE * SROW;
        bf* sVh = buf + 2 * KTILE * SROW;
        bf* sVl = buf + 3 * KTILE * SROW;

        if (kt + 1 < nkt) prefetch(kt + 1);   // LDGs overlap MMAs below

        if (kt <= ktmax_warp) {
            float s[8][4];
            #pragma unroll
            for (int nt = 0; nt < 8; nt++)
                #pragma unroll
                for (int e = 0; e < 4; e++) s[nt][e] = 0.0f;

            #pragma unroll
            for (int ks = 0; ks < 4; ks++) {
                #pragma unroll
                for (int np = 0; np < 4; np++) {
                    uint32_t kh0, kh1, kh2, kh3, kl0, kl1, kl2, kl3;
                    const int addr = (np * 16 + (lane & 15)) * SROW
                                     + ks * 16 + (lane >> 4) * 8;
                    ldsm4(cvta_smem(&sKh[addr]), kh0, kh1, kh2, kh3);
                    ldsm4(cvta_smem(&sKl[addr]), kl0, kl1, kl2, kl3);
                    uint32_t beh[2] = {kh0, kh2}, boh[2] = {kh1, kh3};
                    uint32_t bel[2] = {kl0, kl2}, bol[2] = {kl1, kl3};
                    mma_bf16(s[2*np],   qh[ks], beh);
                    mma_bf16(s[2*np],   qh[ks], bel);
                    mma_bf16(s[2*np],   ql[ks], beh);
                    mma_bf16(s[2*np+1], qh[ks], boh);
                    mma_bf16(s[2*np+1], qh[ks], bol);
                    mma_bf16(s[2*np+1], ql[ks], boh);
                }
            }

            if (kt * KTILE + 63 > base) {
                const int ra = base + (lane >> 2);
                #pragma unroll
                for (int nt = 0; nt < 8; nt++) {
                    const int kc = kt * KTILE + nt * 8 + (lane & 3) * 2;
                    if (kc > ra)      s[nt][0] = -1e30f;
                    if (kc + 1 > ra)  s[nt][1] = -1e30f;
                    if (kc > ra + 8)     s[nt][2] = -1e30f;
                    if (kc + 1 > ra + 8) s[nt][3] = -1e30f;
                }
            }

            float ta = -1e30f, tb = -1e30f;
            #pragma unroll
            for (int nt = 0; nt < 8; nt++) {
                ta = fmaxf(ta, fmaxf(s[nt][0], s[nt][1]));
                tb = fmaxf(tb, fmaxf(s[nt][2], s[nt][3]));
            }
            ta = fmaxf(ta, __shfl_xor_sync(0xffffffffu, ta, 1));
            ta = fmaxf(ta, __shfl_xor_sync(0xffffffffu, ta, 2));
            tb = fmaxf(tb, __shfl_xor_sync(0xffffffffu, tb, 1));
            tb = fmaxf(tb, __shfl_xor_sync(0xffffffffu, tb, 2));

            const float mna = fmaxf(m_a, ta);
            const float mnb = fmaxf(m_b, tb);
            const float ca = __expf((m_a - mna) * SM_SCALE);
            const float cb = __expf((m_b - mnb) * SM_SCALE);
            m_a = mna; m_b = mnb;
            l_a *= ca; l_b *= cb;
            #pragma unroll
            for (int nt = 0; nt < 8; nt++) {
                o[nt][0] *= ca; o[nt][1] *= ca;
                o[nt][2] *= cb; o[nt][3] *= cb;
            }

            float sa = 0.0f, sb = 0.0f;
            #pragma unroll
            for (int nt = 0; nt < 8; nt++) {
                float p0 = __expf((s[nt][0] - mna) * SM_SCALE);
                float p1 = __expf((s[nt][1] - mna) * SM_SCALE);
                float p2 = __expf((s[nt][2] - mnb) * SM_SCALE);
                float p3 = __expf((s[nt][3] - mnb) * SM_SCALE);
                s[nt][0] = p0; s[nt][1] = p1; s[nt][2] = p2; s[nt][3] = p3;
                sa += p0 + p1; sb += p2 + p3;
            }
            sa += __shfl_xor_sync(0xffffffffu, sa, 1);
            sa += __shfl_xor_sync(0xffffffffu, sa, 2);
            sb += __shfl_xor_sync(0xffffffffu, sb, 1);
            sb += __shfl_xor_sync(0xffffffffu, sb, 2);
            l_a += sa; l_b += sb;

            #pragma unroll
            for (int ks = 0; ks < 4; ks++) {
                uint32_t pah[4], pal[4];
                split2(s[2*ks][0],   s[2*ks][1],   pah[0], pal[0]);
                split2(s[2*ks][2],   s[2*ks][3],   pah[1], pal[1]);
                split2(s[2*ks+1][0], s[2*ks+1][1], pah[2], pal[2]);
                split2(s[2*ks+1][2], s[2*ks+1][3], pah[3], pal[3]);
                #pragma unroll
                for (int np = 0; np < 4; np++) {
                    uint32_t vh0, vh1, vh2, vh3, vl0, vl1, vl2, vl3;
                    const int addr = (ks * 16 + (lane & 15)) * SROW
                                     + np * 16 + (lane >> 4) * 8;
                    ldsm4t(cvta_smem(&sVh[addr]), vh0, vh1, vh2, vh3);
                    ldsm4t(cvta_smem(&sVl[addr]), vl0, vl1, vl2, vl3);
                    uint32_t veh[2] = {vh0, vh1}, voh[2] = {vh2, vh3};
                    uint32_t vel[2] = {vl0, vl1}, vol[2] = {vl2, vl3};
                    mma_bf16(o[2*np],   pah, veh);
                    mma_bf16(o[2*np],   pah, vel);
                    mma_bf16(o[2*np],   pal, veh);
                    mma_bf16(o[2*np+1], pah, voh);
                    mma_bf16(o[2*np+1], pah, vol);
                    mma_bf16(o[2*np+1], pal, voh);
                }
            }
        }

        if (kt + 1 < nkt) stash(dsm + ((kt + 1) & 1) * KVBUF);
        __syncthreads();
    }

    const float ia = 1.0f / l_a;
    const float ib = 1.0f / l_b;
    const int ra = base + (lane >> 2);
    const size_t rowa = (batch_row + ra) * (size_t)DMODEL + h * HDIM;
    const size_t rowb = rowa + 8 * DMODEL;
    #pragma unroll
    for (int nt = 0; nt < 8; nt++) {
        const int col = nt * 8 + (lane & 3) * 2;
        uint32_t hi, lo;
        split2(o[nt][0] * ia, o[nt][1] * ia, hi, lo);
        *(uint32_t*)(out_hi + rowa + col) = hi;
        *(uint32_t*)(out_lo + rowa + col) = lo;
        split2(o[nt][2] * ib, o[nt][3] * ib, hi, lo);
        *(uint32_t*)(out_hi + rowb + col) = hi;
        *(uint32_t*)(out_lo + rowb + col) = lo;
    }
}

// ---------------------------------------------------------------------------
// LayerNorm over last dim, in-place. One block (256 thr) per row of 1024.
// ---------------------------------------------------------------------------
__global__ __launch_bounds__(256) void ln_kernel(
    float* __restrict__ io, const float* __restrict__ gamma,
    const float* __restrict__ beta)
{
    const int row = blockIdx.x;
    const int tid = threadIdx.x;
    float4* p = (float4*)(io + (size_t)row * DMODEL);
    float4 v = p[tid];

    float s  = v.x + v.y + v.z + v.w;
    float s2 = fmaf(v.x, v.x, fmaf(v.y, v.y, fmaf(v.z, v.z, v.w * v.w)));

    #pragma unroll
    for (int ofs = 16; ofs; ofs >>= 1) {
        s  += __shfl_xor_sync(0xffffffffu, s, ofs);
        s2 += __shfl_xor_sync(0xffffffffu, s2, ofs);
    }
    __shared__ float shs[8], shs2[8];
    const int w = tid >> 5, l = tid & 31;
    if (l == 0) { shs[w] = s; shs2[w] = s2; }
    __syncthreads();
    if (tid < 32) {
        float a  = (l < 8) ? shs[l]  : 0.0f;
        float a2 = (l < 8) ? shs2[l] : 0.0f;
        #pragma unroll
        for (int ofs = 4; ofs; ofs >>= 1) {
            a  += __shfl_xor_sync(0xffffffffu, a, ofs);
            a2 += __shfl_xor_sync(0xffffffffu, a2, ofs);
        }
        if (l == 0) { shs[0] = a; shs2[0] = a2; }
    }
    __syncthreads();

    const float mean = shs[0] * (1.0f / DMODEL);
    const float var  = shs2[0] * (1.0f / DMODEL) - mean * mean;
    const float rstd = rsqrtf(var + LN_EPS);

    float4 g  = ((const float4*)gamma)[tid];
    float4 be = ((const float4*)beta)[tid];
    float4 r;
    r.x = (v.x - mean) * rstd * g.x + be.x;
    r.y = (v.y - mean) * rstd * g.y + be.y;
    r.z = (v.z - mean) * rstd * g.z + be.z;
    r.w = (v.w - mean) * rstd * g.w + be.w;
    p[tid] = r;
}

// ---------------------------------------------------------------------------
extern "C" void kernel_launch(void* const* d_in, const int* in_sizes, int n_in,
                              void* d_out, int out_size)
{
    const float* x     = (const float*)d_in[0];
    const float* Wqkv  = (const float*)d_in[1];
    const float* bqkv  = (const float*)d_in[2];
    const float* Wout  = (const float*)d_in[3];
    const float* bout  = (const float*)d_in[4];
    const float* gamma = (const float*)d_in[5];
    const float* beta  = (const float*)d_in[6];
    float* out = (float*)d_out;

    bf *xhi, *xlo, *wqh, *wql, *woh, *wol, *qh, *qlo, *ahi, *alo;
    cudaGetSymbolAddress((void**)&xhi, g_xhi);
    cudaGetSymbolAddress((void**)&xlo, g_xlo);
    cudaGetSymbolAddress((void**)&wqh, g_wqkv_hi);
    cudaGetSymbolAddress((void**)&wql, g_wqkv_lo);
    cudaGetSymbolAddress((void**)&woh, g_wout_hi);
    cudaGetSymbolAddress((void**)&wol, g_wout_lo);
    cudaGetSymbolAddress((void**)&qh,  g_qkv_hi);
    cudaGetSymbolAddress((void**)&qlo, g_qkv_lo);
    cudaGetSymbolAddress((void**)&ahi, g_attn_hi);
    cudaGetSymbolAddress((void**)&alo, g_attn_lo);

    static bool attrs_set = false;
    if (!attrs_set) {
        cudaFuncSetAttribute(mma_gemm<false, true>,
                             cudaFuncAttributeMaxDynamicSharedMemorySize, GSMEM_BYTES);
        cudaFuncSetAttribute(mma_gemm<true, false>,
                             cudaFuncAttributeMaxDynamicSharedMemorySize, GSMEM_BYTES);
        cudaFuncSetAttribute(attn_mma,
                             cudaFuncAttributeMaxDynamicSharedMemorySize, ASMEM_BYTES);
        attrs_set = true;
    }

    // 0) fp32 -> bf16 hi/lo splits of inputs
    {
        int n4 = MROWS * DMODEL / 4;
        cvt_kernel<<<(n4 + 255) / 256, 256>>>((const float4*)x, (uint2*)xhi, (uint2*)xlo, n4);
        n4 = DMODEL * QKV_N / 4;
        cvt_kernel<<<(n4 + 255) / 256, 256>>>((const float4*)Wqkv, (uint2*)wqh, (uint2*)wql, n4);
        n4 = DMODEL * DMODEL / 4;
        cvt_kernel<<<(n4 + 255) / 256, 256>>>((const float4*)Wout, (uint2*)woh, (uint2*)wol, n4);
    }
    // 1) QKV projection -> split bf16 output
    {
        dim3 grid(QKV_N / BN, MROWS / BM);
        mma_gemm<false, true><<<grid, 256, GSMEM_BYTES>>>(
            xhi, xlo, wqh, wql, bqkv, nullptr, nullptr, qh, qlo,
            MROWS, QKV_N, DMODEL);
    }
    // 2) tensor-core causal flash attention -> split bf16 output
    {
        dim3 grid(SLEN / QTILE, NHEADS, BATCH);
        attn_mma<<<grid, 256, ASMEM_BYTES>>>(qh, qlo, ahi, alo);
    }
    // 3) out projection + bias + residual -> fp32
    {
        dim3 grid(DMODEL / BN, MROWS / BM);
        mma_gemm<true, false><<<grid, 256, GSMEM_BYTES>>>(
            ahi, alo, woh, wol, bout, x, out, nullptr, nullptr,
            MROWS, DMODEL, DMODEL);
    }
    // 4) LayerNorm in-place on d_out
    ln_kernel<<<MROWS, 256>>>(out, gamma, beta);
}